// round 11
// baseline (speedup 1.0000x reference)
#include <cuda_runtime.h>
#include <cuda_bf16.h>
#include <cstdint>
#include <math.h>

#define NQ    2048
#define DIM   256
#define NF    100000
#define NCLS  1000
#define KSEL  16
#define TAUF  0.2f
#define LSCALE 20.0f

#define BM 64
#define BN 128
#define NSTRIPE 37
#define TBASE 21             // tiles per stripe (first 5 stripes get +1)
#define KP 8                 // per (row, col-quarter) candidates per stripe
#define NCAND (NSTRIPE*4*KP) // 1184
#define CSEL 32

#define NT 256               // threads per CTA (8 warps), 2 CTAs/SM

// smem layout (bytes, dynamic)
#define SM_A   0                 // 64 x 256 bf16 blocked+swizzled : 32768
#define SM_B   32768             // ring of 3 x (128 x 64 bf16)    : 49152
#define SM_S   81920             // 1 x (64 x 136 bf16) sims       : 17408
#define SROW   272
#define SM_TOTAL 99328

// ---------------- device scratch ----------------
__device__ __nv_bfloat16 g_xb[NQ*DIM];
__device__ float         g_xn[NQ*DIM];
__device__ __nv_bfloat16 g_mb[(size_t)NF*DIM];
__device__ float         g_cval[(size_t)NQ*NCAND];
__device__ int           g_cidx[(size_t)NQ*NCAND];

// ---------------- PTX helpers ----------------
__device__ __forceinline__ void cpa16(unsigned dst, const void* src, int sz){
  asm volatile("cp.async.cg.shared.global [%0], [%1], 16, %2;\n"
    :: "r"(dst), "l"(__cvta_generic_to_global(src)), "r"(sz));
}
__device__ __forceinline__ void cpa_commit(){ asm volatile("cp.async.commit_group;\n"); }
template<int N> __device__ __forceinline__ void cpa_wait(){
  asm volatile("cp.async.wait_group %0;\n" :: "n"(N));
}
__device__ __forceinline__ void ldsm4(uint32_t* r, unsigned addr){
  asm volatile("ldmatrix.sync.aligned.m8n8.x4.shared.b16 {%0,%1,%2,%3}, [%4];\n"
    : "=r"(r[0]), "=r"(r[1]), "=r"(r[2]), "=r"(r[3]) : "r"(addr));
}
__device__ __forceinline__ void mma16816(float* d, const uint32_t* a, uint32_t b0, uint32_t b1){
  asm volatile(
    "mma.sync.aligned.m16n8k16.row.col.f32.bf16.bf16.f32 "
    "{%0,%1,%2,%3}, {%4,%5,%6,%7}, {%8,%9}, {%0,%1,%2,%3};\n"
    : "+f"(d[0]), "+f"(d[1]), "+f"(d[2]), "+f"(d[3])
    : "r"(a[0]), "r"(a[1]), "r"(a[2]), "r"(a[3]), "r"(b0), "r"(b1));
}

// ---------------- kernel 1: setup ----------------
__global__ void setup_kernel(const float* __restrict__ x, const float* __restrict__ mean,
                             const float* __restrict__ stdv, const float* __restrict__ mf){
  {
    int stride = gridDim.x * blockDim.x;
    int n4 = NF*DIM/4;
    for (int i = blockIdx.x*blockDim.x + threadIdx.x; i < n4; i += stride){
      float4 f = ((const float4*)mf)[i];
      __nv_bfloat162* o = (__nv_bfloat162*)g_mb;
      o[2*i]   = __floats2bfloat162_rn(f.x, f.y);
      o[2*i+1] = __floats2bfloat162_rn(f.z, f.w);
    }
  }
  int r = blockIdx.x, t = threadIdx.x;
  float v = (x[r*DIM + t] - mean[t]) / stdv[t];
  float s = v*v;
  #pragma unroll
  for (int o = 16; o; o >>= 1) s += __shfl_xor_sync(0xffffffffu, s, o);
  __shared__ float ws[8];
  __shared__ float nrm;
  if ((t & 31) == 0) ws[t >> 5] = s;
  __syncthreads();
  if (t == 0){
    float tot = 0.f;
    #pragma unroll
    for (int i = 0; i < 8; i++) tot += ws[i];
    nrm = fmaxf(sqrtf(tot), 1e-6f);
  }
  __syncthreads();
  float o = v / nrm;
  g_xn[r*DIM + t] = o;
  g_xb[r*DIM + t] = __float2bfloat16(o);
}

// ---------------- kernel 2: GEMM + interleaved top-k, 2 CTAs/SM ----------------
__device__ __forceinline__ void load_B_chunk(unsigned sBu, int buf, int nb, int kc, int t){
  unsigned bbase = sBu + (unsigned)buf * 16384u;
  #pragma unroll
  for (int i = 0; i < 4; i++){
    int id = t + NT*i;
    int r = id >> 3, c = id & 7;
    int fr = nb + r;
    int ok = (fr < NF);
    cpa16(bbase + (unsigned)((r*8 + ((c ^ r) & 7)) * 16),
          g_mb + (size_t)(ok ? fr : 0) * DIM + kc*64 + c*8, ok ? 16 : 0);
  }
}

__global__ void __launch_bounds__(NT, 2) gemm_topk_kernel(){
  extern __shared__ char smem[];
  const unsigned sA_u = (unsigned)__cvta_generic_to_shared(smem);
  const unsigned sBu  = sA_u + SM_B;

  int t = threadIdx.x, lane = t & 31, w = t >> 5;
  int m0 = blockIdx.x * BM;
  int y  = blockIdx.y;
  int t0 = y * TBASE + min(y, 5);
  int ntiles = TBASE + (y < 5 ? 1 : 0);

  // scan identity: 4 threads per row, 32 cols each
  int srow = t & 63;
  int squad = t >> 6;

  float tv[KP]; int ti[KP];
  #pragma unroll
  for (int i = 0; i < KP; i++){ tv[i] = -INFINITY; ti[i] = 0; }
  float tmin = -INFINITY; int minpos = 0;

  // scan one 8-col chunk (one uint4) with hmax2 fast-reject
  auto scan_chunk = [&](int nb, int kc){
    uint4 d = *(const uint4*)(smem + SM_S + srow*SROW + squad*64 + kc*16);
    __nv_bfloat162 v0 = *(__nv_bfloat162*)&d.x;
    __nv_bfloat162 v1 = *(__nv_bfloat162*)&d.y;
    __nv_bfloat162 v2 = *(__nv_bfloat162*)&d.z;
    __nv_bfloat162 v3 = *(__nv_bfloat162*)&d.w;
    __nv_bfloat162 mm = __hmax2(__hmax2(v0, v1), __hmax2(v2, v3));
    float mx = __bfloat162float(__hmax(mm.x, mm.y));
    if (mx > tmin){
      uint32_t word[4] = {d.x, d.y, d.z, d.w};
      int cbase = nb + squad*32 + kc*8;
      #pragma unroll
      for (int h = 0; h < 4; h++){
        float2 f = __bfloat1622float2(*(__nv_bfloat162*)&word[h]);
        int gc0 = cbase + 2*h;
        if (f.x > tmin && gc0 < NF){
          #pragma unroll
          for (int q = 0; q < KP; q++) if (q == minpos){ tv[q] = f.x; ti[q] = gc0; }
          tmin = tv[0]; minpos = 0;
          #pragma unroll
          for (int q = 1; q < KP; q++) if (tv[q] < tmin){ tmin = tv[q]; minpos = q; }
        }
        if (f.y > tmin && gc0 + 1 < NF){
          #pragma unroll
          for (int q = 0; q < KP; q++) if (q == minpos){ tv[q] = f.y; ti[q] = gc0 + 1; }
          tmin = tv[0]; minpos = 0;
          #pragma unroll
          for (int q = 1; q < KP; q++) if (tv[q] < tmin){ tmin = tv[q]; minpos = q; }
        }
      }
    }
  };

  // prologue: A tile (64x256) + first 2 B stages
  #pragma unroll
  for (int i = 0; i < 8; i++){
    int id = t + NT*i;
    int row = id >> 5, c = id & 31;
    int phys = (c & 24) | ((c ^ row) & 7);
    cpa16(sA_u + (unsigned)((row*32 + phys)*16),
          g_xb + (size_t)(m0 + row)*DIM + c*8, 16);
  }
  load_B_chunk(sBu, 0, (t0 + 0)*BN, 0, t);
  cpa_commit();
  load_B_chunk(sBu, 1, (t0 + 0)*BN, 1, t);
  cpa_commit();

  int wr = (w >> 2) * 32;     // warp rows [wr, wr+32)
  int wc = (w & 3) * 32;      // warp cols [wc, wc+32)
  int total = ntiles * 4;
  int hi = lane >> 4;
  int lo15 = lane & 15;

  // precompute B smem offsets (kc-invariant): boff[ss][p]
  unsigned boff[4][2];
  #pragma unroll
  for (int ss = 0; ss < 4; ss++){
    #pragma unroll
    for (int p = 0; p < 2; p++){
      int row = wc + 16*p + lo15;
      int c = 2*ss + hi;
      int phys = (c ^ row) & 7;
      boff[ss][p] = (unsigned)((row*8 + phys)*16);
    }
  }
  unsigned arow[2];
  #pragma unroll
  for (int mf = 0; mf < 2; mf++) arow[mf] = (unsigned)(wr + 16*mf + lo15);

  auto frag_load = [&](int kc, int ss, uint32_t af[2][4], uint32_t bv[2][4], unsigned bbase){
    int c = kc*8 + 2*ss + hi;
    #pragma unroll
    for (int mf = 0; mf < 2; mf++){
      int row = arow[mf];
      int phys = (c & 24) | ((c ^ row) & 7);
      ldsm4(af[mf], sA_u + (unsigned)((row*32 + phys)*16));
    }
    #pragma unroll
    for (int p = 0; p < 2; p++){
      uint32_t r[4];
      ldsm4(r, bbase + boff[ss][p]);
      bv[0][2*p] = r[0]; bv[0][2*p+1] = r[1];
      bv[1][2*p] = r[2]; bv[1][2*p+1] = r[3];
    }
  };

  for (int i = 0; i < ntiles; i++){
    float acc[2][4][4];
    #pragma unroll
    for (int mf = 0; mf < 2; mf++)
      #pragma unroll
      for (int nf = 0; nf < 4; nf++)
        #pragma unroll
        for (int q = 0; q < 4; q++) acc[mf][nf][q] = 0.f;

    #pragma unroll
    for (int kc = 0; kc < 4; kc++){
      int s = i*4 + kc;
      cpa_wait<1>();                      // stage-s groups complete (this thread)
      __syncthreads();                    // stage-s data visible; stage s-1 readers done
      int sn = s + 2;
      if (sn < total){
        // buffer (s+2)%3 == (s-1)%3, whose readers finished before this sync
        int sm3 = sn; sm3 = sm3 - (sm3/3)*3;
        load_B_chunk(sBu, sm3, (t0 + (sn >> 2))*BN, sn & 3, t);
      }
      cpa_commit();

      int cb = s - (s/3)*3;
      unsigned bbase = sBu + (unsigned)cb * 16384u;

      // software-pipelined fragments
      uint32_t afb[2][2][4], bvb[2][2][4];
      frag_load(kc, 0, afb[0], bvb[0], bbase);
      #pragma unroll
      for (int ss = 0; ss < 4; ss++){
        int cur = ss & 1;
        if (ss < 3) frag_load(kc, ss + 1, afb[cur ^ 1], bvb[cur ^ 1], bbase);
        if (ss == 0 && i > 0) scan_chunk((t0 + i - 1)*BN, kc);
        #pragma unroll
        for (int mf = 0; mf < 2; mf++)
          #pragma unroll
          for (int nf = 0; nf < 4; nf++)
            mma16816(acc[mf][nf], afb[cur][mf], bvb[cur][0][nf], bvb[cur][1][nf]);
      }
    }

    // all scans of tile i-1 done by all threads before overwriting sims buffer
    __syncthreads();

    // dump sims tile i (bf16) into the single sims buffer
    int r0r = wr + (lane >> 2);
    int c0c = wc + 2*(lane & 3);
    #pragma unroll
    for (int mf = 0; mf < 2; mf++){
      #pragma unroll
      for (int nf = 0; nf < 4; nf++){
        int rr = r0r + 16*mf, cc = c0c + 8*nf;
        __nv_bfloat162 p0 = __floats2bfloat162_rn(acc[mf][nf][0], acc[mf][nf][1]);
        __nv_bfloat162 p1 = __floats2bfloat162_rn(acc[mf][nf][2], acc[mf][nf][3]);
        *(__nv_bfloat162*)(smem + SM_S + rr*SROW + cc*2) = p0;
        *(__nv_bfloat162*)(smem + SM_S + (rr+8)*SROW + cc*2) = p1;
      }
    }
  }

  // epilogue: scan last tile (dump must be visible)
  __syncthreads();
  {
    int i = ntiles - 1;
    #pragma unroll
    for (int kc = 0; kc < 4; kc++) scan_chunk((t0 + i)*BN, kc);
  }

  size_t base = (size_t)(m0 + srow) * NCAND + (size_t)y * (4*KP) + (size_t)squad * KP;
  #pragma unroll
  for (int i = 0; i < KP; i++){ g_cval[base + i] = tv[i]; g_cidx[base + i] = ti[i]; }
}

// ---------------- kernel 3: merge + exact rescore + softmax + scatter ----------------
__global__ void __launch_bounds__(128) merge_kernel(const float* __restrict__ mf,
                                                    const int* __restrict__ lab,
                                                    float* __restrict__ out){
  int row = blockIdx.x, t = threadIdx.x, lane = t & 31, w = t >> 5;
  __shared__ float cv[NCAND];
  __shared__ int   ci[NCAND];
  __shared__ float xs[DIM];
  __shared__ float accs[NCLS];
  __shared__ int   selIdx[CSEL];
  __shared__ float ex[CSEL];
  __shared__ float wgt[KSEL]; __shared__ int flab[KSEL];

  for (int j = t; j < NCAND; j += 128){
    cv[j] = g_cval[(size_t)row*NCAND + j];
    ci[j] = g_cidx[(size_t)row*NCAND + j];
  }
  for (int j = t; j < DIM; j += 128) xs[j] = g_xn[row*DIM + j];
  for (int c = t; c < NCLS; c += 128) accs[c] = 0.f;
  __syncthreads();

  if (w == 0){
    for (int it = 0; it < CSEL; it++){
      float bv = -INFINITY; int bp = 0;
      for (int j = lane; j < NCAND; j += 32){
        float c = cv[j];
        if (c > bv){ bv = c; bp = j; }
      }
      #pragma unroll
      for (int o = 16; o; o >>= 1){
        float ov = __shfl_xor_sync(0xffffffffu, bv, o);
        int   op = __shfl_xor_sync(0xffffffffu, bp, o);
        if (ov > bv || (ov == bv && op < bp)){ bv = ov; bp = op; }
      }
      if (lane == 0){ selIdx[it] = ci[bp]; cv[bp] = -INFINITY; }
      __syncwarp();
    }
  }
  __syncthreads();

  for (int rr = 0; rr < CSEL/4; rr++){
    int c = w + 4*rr;
    const float* fr = mf + (size_t)selIdx[c] * DIM;
    float s = 0.f;
    #pragma unroll
    for (int j = 0; j < 8; j++){ int k = lane + 32*j; s += fr[k] * xs[k]; }
    #pragma unroll
    for (int o = 16; o; o >>= 1) s += __shfl_down_sync(0xffffffffu, s, o);
    if (lane == 0) ex[c] = s;
  }
  __syncthreads();

  if (t == 0){
    unsigned um = 0;
    float sval[KSEL]; int sfeat[KSEL];
    for (int it = 0; it < KSEL; it++){
      float bv = -INFINITY; int bc = 0;
      for (int c = 0; c < CSEL; c++){
        if (!((um >> c) & 1u) && ex[c] > bv){ bv = ex[c]; bc = c; }
      }
      um |= 1u << bc;
      sval[it] = bv; sfeat[it] = selIdx[bc];
    }
    float m = sval[0], sum = 0.f;
    for (int i = 0; i < KSEL; i++){ float e = expf((sval[i]-m)/TAUF); wgt[i] = e; sum += e; }
    float inv = 1.f / sum;
    for (int i = 0; i < KSEL; i++){ wgt[i] *= inv; flab[i] = lab[sfeat[i]]; }
    for (int i = 0; i < KSEL; i++) accs[flab[i]] += wgt[i];
  }
  __syncthreads();
  for (int c = t; c < NCLS; c += 128) out[(size_t)row*NCLS + c] = accs[c] * LSCALE;
}

// ---------------- dummy (profiling alignment: gemm at launch position 3) ----------------
__global__ void dummy_kernel(){}

// ---------------- launch ----------------
extern "C" void kernel_launch(void* const* d_in, const int* in_sizes, int n_in,
                              void* d_out, int out_size){
  const float* x    = (const float*)d_in[0];
  const float* mean = (const float*)d_in[1];
  const float* stdv = (const float*)d_in[2];
  const float* mf   = (const float*)d_in[3];
  const int*   lab  = (const int*)d_in[4];
  float* out = (float*)d_out;

  cudaFuncSetAttribute(gemm_topk_kernel, cudaFuncAttributeMaxDynamicSharedMemorySize, SM_TOTAL);

  setup_kernel<<<NQ, DIM>>>(x, mean, stdv, mf);   // pos 0
  dummy_kernel<<<1, 32>>>();                      // pos 1
  dummy_kernel<<<1, 32>>>();                      // pos 2
  gemm_topk_kernel<<<dim3(NQ/BM, NSTRIPE), NT, SM_TOTAL>>>();  // pos 3
  merge_kernel<<<NQ, 128>>>(mf, lab, out);        // pos 4
}

// round 16
// speedup vs baseline: 1.1342x; 1.1342x over previous
#include <cuda_runtime.h>
#include <cuda_bf16.h>
#include <cstdint>
#include <math.h>

#define NQ    2048
#define DIM   256
#define NF    100000
#define NCLS  1000
#define KSEL  16
#define TAUF  0.2f
#define LSCALE 20.0f

#define BM 128
#define BN 128
#define NSTRIPE 37
#define TBASE 21             // tiles per stripe (first 5 stripes get +1)
#define KP 8                 // per (row, col-quarter) candidates per stripe
#define NCAND (NSTRIPE*4*KP) // 1184
#define CSEL 32

#define NT 512               // threads per CTA (16 warps), 1 CTA/SM

// smem layout (bytes, dynamic)
#define SM_A   0                 // 128 x 256 bf16 blocked+swizzled : 65536
#define SM_B   65536             // 2 x full B tile (128 x 256 bf16): 131072
#define SM_S   196608            // 1 x (128 x 136 bf16) sims       : 34816
#define SROW   272
#define SM_TOTAL 231424          // 226 KB

// ---------------- device scratch ----------------
__device__ __nv_bfloat16 g_xb[NQ*DIM];
__device__ float         g_xn[NQ*DIM];
__device__ __nv_bfloat16 g_mb[(size_t)NF*DIM];
__device__ float         g_cval[(size_t)NQ*NCAND];
__device__ int           g_cidx[(size_t)NQ*NCAND];

// ---------------- PTX helpers ----------------
__device__ __forceinline__ void cpa16(unsigned dst, const void* src, int sz){
  asm volatile("cp.async.cg.shared.global [%0], [%1], 16, %2;\n"
    :: "r"(dst), "l"(__cvta_generic_to_global(src)), "r"(sz));
}
__device__ __forceinline__ void cpa_commit(){ asm volatile("cp.async.commit_group;\n"); }
template<int N> __device__ __forceinline__ void cpa_wait(){
  asm volatile("cp.async.wait_group %0;\n" :: "n"(N));
}
__device__ __forceinline__ void ldsm4(uint32_t* r, unsigned addr){
  asm volatile("ldmatrix.sync.aligned.m8n8.x4.shared.b16 {%0,%1,%2,%3}, [%4];\n"
    : "=r"(r[0]), "=r"(r[1]), "=r"(r[2]), "=r"(r[3]) : "r"(addr));
}
__device__ __forceinline__ void mma16816(float* d, const uint32_t* a, uint32_t b0, uint32_t b1){
  asm volatile(
    "mma.sync.aligned.m16n8k16.row.col.f32.bf16.bf16.f32 "
    "{%0,%1,%2,%3}, {%4,%5,%6,%7}, {%8,%9}, {%0,%1,%2,%3};\n"
    : "+f"(d[0]), "+f"(d[1]), "+f"(d[2]), "+f"(d[3])
    : "r"(a[0]), "r"(a[1]), "r"(a[2]), "r"(a[3]), "r"(b0), "r"(b1));
}

// ---------------- kernel 1: setup ----------------
__global__ void setup_kernel(const float* __restrict__ x, const float* __restrict__ mean,
                             const float* __restrict__ stdv, const float* __restrict__ mf){
  {
    int stride = gridDim.x * blockDim.x;
    int n4 = NF*DIM/4;
    for (int i = blockIdx.x*blockDim.x + threadIdx.x; i < n4; i += stride){
      float4 f = ((const float4*)mf)[i];
      __nv_bfloat162* o = (__nv_bfloat162*)g_mb;
      o[2*i]   = __floats2bfloat162_rn(f.x, f.y);
      o[2*i+1] = __floats2bfloat162_rn(f.z, f.w);
    }
  }
  int r = blockIdx.x, t = threadIdx.x;
  float v = (x[r*DIM + t] - mean[t]) / stdv[t];
  float s = v*v;
  #pragma unroll
  for (int o = 16; o; o >>= 1) s += __shfl_xor_sync(0xffffffffu, s, o);
  __shared__ float ws[8];
  __shared__ float nrm;
  if ((t & 31) == 0) ws[t >> 5] = s;
  __syncthreads();
  if (t == 0){
    float tot = 0.f;
    #pragma unroll
    for (int i = 0; i < 8; i++) tot += ws[i];
    nrm = fmaxf(sqrtf(tot), 1e-6f);
  }
  __syncthreads();
  float o = v / nrm;
  g_xn[r*DIM + t] = o;
  g_xb[r*DIM + t] = __float2bfloat16(o);
}

// ---------------- kernel 2: GEMM + top-k, whole-tile B, 2 syncs/tile ----------------
__device__ __forceinline__ void load_B_tile(unsigned sBu, int buf, int nb, int t){
  unsigned bbase = sBu + (unsigned)buf * 65536u;
  #pragma unroll
  for (int j = 0; j < 8; j++){
    int id = t + NT*j;             // 0..4095
    int q = id >> 10;              // 64-k chunk 0..3
    int r = (id >> 3) & 127;       // feature row
    int c = id & 7;                // 16B col within chunk
    int fr = nb + r;
    int ok = (fr < NF);
    cpa16(bbase + (unsigned)(q*16384 + (r*8 + ((c ^ r) & 7)) * 16),
          g_mb + (size_t)(ok ? fr : 0) * DIM + q*64 + c*8, ok ? 16 : 0);
  }
}

__global__ void __launch_bounds__(NT, 1) gemm_topk_kernel(){
  extern __shared__ char smem[];
  const unsigned sA_u = (unsigned)__cvta_generic_to_shared(smem);
  const unsigned sBu  = sA_u + SM_B;

  int t = threadIdx.x, lane = t & 31, w = t >> 5;
  int m0 = blockIdx.x * BM;
  int y  = blockIdx.y;
  int t0 = y * TBASE + min(y, 5);
  int ntiles = TBASE + (y < 5 ? 1 : 0);

  // scan identity: 4 threads per row, 32 cols each
  int srow = t & 127;
  int squad = t >> 7;

  float tv[KP]; int ti[KP];
  #pragma unroll
  for (int i = 0; i < KP; i++){ tv[i] = -INFINITY; ti[i] = 0; }
  float tmin = -INFINITY; int minpos = 0;

  // scan one 8-col chunk (one uint4) with hmax2 fast-reject
  auto scan_chunk = [&](int nb, int q){
    uint4 d = *(const uint4*)(smem + SM_S + srow*SROW + squad*64 + q*16);
    __nv_bfloat162 v0 = *(__nv_bfloat162*)&d.x;
    __nv_bfloat162 v1 = *(__nv_bfloat162*)&d.y;
    __nv_bfloat162 v2 = *(__nv_bfloat162*)&d.z;
    __nv_bfloat162 v3 = *(__nv_bfloat162*)&d.w;
    __nv_bfloat162 mm = __hmax2(__hmax2(v0, v1), __hmax2(v2, v3));
    float mx = __bfloat162float(__hmax(mm.x, mm.y));
    if (mx > tmin){
      uint32_t word[4] = {d.x, d.y, d.z, d.w};
      int cbase = nb + squad*32 + q*8;
      #pragma unroll
      for (int h = 0; h < 4; h++){
        float2 f = __bfloat1622float2(*(__nv_bfloat162*)&word[h]);
        int gc0 = cbase + 2*h;
        if (f.x > tmin && gc0 < NF){
          #pragma unroll
          for (int qq = 0; qq < KP; qq++) if (qq == minpos){ tv[qq] = f.x; ti[qq] = gc0; }
          tmin = tv[0]; minpos = 0;
          #pragma unroll
          for (int qq = 1; qq < KP; qq++) if (tv[qq] < tmin){ tmin = tv[qq]; minpos = qq; }
        }
        if (f.y > tmin && gc0 + 1 < NF){
          #pragma unroll
          for (int qq = 0; qq < KP; qq++) if (qq == minpos){ tv[qq] = f.y; ti[qq] = gc0 + 1; }
          tmin = tv[0]; minpos = 0;
          #pragma unroll
          for (int qq = 1; qq < KP; qq++) if (tv[qq] < tmin){ tmin = tv[qq]; minpos = qq; }
        }
      }
    }
  };

  // prologue: A tile + B tile0 (group 0), B tile1 (group 1)
  #pragma unroll
  for (int j = 0; j < 8; j++){
    int id = t + NT*j;
    int row = id >> 5, c = id & 31;
    int phys = (c & 24) | ((c ^ row) & 7);
    cpa16(sA_u + (unsigned)((row*32 + phys)*16),
          g_xb + (size_t)(m0 + row)*DIM + c*8, 16);
  }
  load_B_tile(sBu, 0, (t0 + 0)*BN, t);
  cpa_commit();
  if (ntiles > 1) load_B_tile(sBu, 1, (t0 + 1)*BN, t);
  cpa_commit();

  int wr = (w >> 2) * 32;     // warp rows [wr, wr+32)
  int wc = (w & 3) * 32;      // warp cols [wc, wc+32)
  int hi = lane >> 4;
  int lo15 = lane & 15;

  // precompute B smem offsets: boff[ss][p] (within a 64-k chunk)
  unsigned boff[4][2];
  #pragma unroll
  for (int ss = 0; ss < 4; ss++){
    #pragma unroll
    for (int p = 0; p < 2; p++){
      int row = wc + 16*p + lo15;
      int c = 2*ss + hi;
      int phys = (c ^ row) & 7;
      boff[ss][p] = (unsigned)((row*8 + phys)*16);
    }
  }
  unsigned arow[2];
  #pragma unroll
  for (int mf = 0; mf < 2; mf++) arow[mf] = (unsigned)(wr + 16*mf + lo15);

  // fragment loader for flat step (q = step>>2, ss = step&3)
  auto frag_load = [&](int step, uint32_t af[2][4], uint32_t bv[2][4], unsigned tb){
    int q = step >> 2, ss = step & 3;
    int c = q*8 + 2*ss + hi;
    #pragma unroll
    for (int mf = 0; mf < 2; mf++){
      int row = arow[mf];
      int phys = (c & 24) | ((c ^ row) & 7);
      ldsm4(af[mf], sA_u + (unsigned)((row*32 + phys)*16));
    }
    unsigned bbase = tb + (unsigned)(q * 16384);
    #pragma unroll
    for (int p = 0; p < 2; p++){
      uint32_t r[4];
      ldsm4(r, bbase + boff[ss][p]);
      bv[0][2*p] = r[0]; bv[0][2*p+1] = r[1];
      bv[1][2*p] = r[2]; bv[1][2*p+1] = r[3];
    }
  };

  for (int i = 0; i < ntiles; i++){
    cpa_wait<1>();                 // B tile i arrived (tile i+1 may be pending)
    __syncthreads();               // visible to all; dump(i-1) visible too

    unsigned tb = sBu + (unsigned)(i & 1) * 65536u;
    float acc[2][4][4];
    #pragma unroll
    for (int mf = 0; mf < 2; mf++)
      #pragma unroll
      for (int nf = 0; nf < 4; nf++)
        #pragma unroll
        for (int q = 0; q < 4; q++) acc[mf][nf][q] = 0.f;

    // one uninterrupted 16-step mma burst, fragments double-buffered
    uint32_t afb[2][2][4], bvb[2][2][4];
    frag_load(0, afb[0], bvb[0], tb);
    #pragma unroll
    for (int step = 0; step < 16; step++){
      int cur = step & 1;
      if (step < 15) frag_load(step + 1, afb[cur ^ 1], bvb[cur ^ 1], tb);
      if ((step & 3) == 0 && i > 0) scan_chunk((t0 + i - 1)*BN, step >> 2);
      #pragma unroll
      for (int mf = 0; mf < 2; mf++)
        #pragma unroll
        for (int nf = 0; nf < 4; nf++)
          mma16816(acc[mf][nf], afb[cur][mf], bvb[cur][0][nf], bvb[cur][1][nf]);
    }

    __syncthreads();               // all B-tile reads + all scans(i-1) done

    // prefetch tile i+2 into buffer (i&1)
    if (i + 2 < ntiles) load_B_tile(sBu, i & 1, (t0 + i + 2)*BN, t);
    cpa_commit();                  // commit even when empty: keeps group counting aligned

    // dump sims tile i (bf16) into the single sims buffer
    int r0r = wr + (lane >> 2);
    int c0c = wc + 2*(lane & 3);
    #pragma unroll
    for (int mf = 0; mf < 2; mf++){
      #pragma unroll
      for (int nf = 0; nf < 4; nf++){
        int rr = r0r + 16*mf, cc = c0c + 8*nf;
        __nv_bfloat162 p0 = __floats2bfloat162_rn(acc[mf][nf][0], acc[mf][nf][1]);
        __nv_bfloat162 p1 = __floats2bfloat162_rn(acc[mf][nf][2], acc[mf][nf][3]);
        *(__nv_bfloat162*)(smem + SM_S + rr*SROW + cc*2) = p0;
        *(__nv_bfloat162*)(smem + SM_S + (rr+8)*SROW + cc*2) = p1;
      }
    }
  }

  // epilogue: scan last tile
  __syncthreads();
  #pragma unroll
  for (int q = 0; q < 4; q++) scan_chunk((t0 + ntiles - 1)*BN, q);

  size_t base = (size_t)(m0 + srow) * NCAND + (size_t)y * (4*KP) + (size_t)squad * KP;
  #pragma unroll
  for (int i = 0; i < KP; i++){ g_cval[base + i] = tv[i]; g_cidx[base + i] = ti[i]; }
}

// ---------------- kernel 3: merge + exact rescore + softmax + scatter ----------------
__global__ void __launch_bounds__(128) merge_kernel(const float* __restrict__ mf,
                                                    const int* __restrict__ lab,
                                                    float* __restrict__ out){
  int row = blockIdx.x, t = threadIdx.x, lane = t & 31, w = t >> 5;
  __shared__ float cv[NCAND];
  __shared__ int   ci[NCAND];
  __shared__ float xs[DIM];
  __shared__ float accs[NCLS];
  __shared__ int   selIdx[CSEL];
  __shared__ float ex[CSEL];
  __shared__ float wgt[KSEL]; __shared__ int flab[KSEL];

  for (int j = t; j < NCAND; j += 128){
    cv[j] = g_cval[(size_t)row*NCAND + j];
    ci[j] = g_cidx[(size_t)row*NCAND + j];
  }
  for (int j = t; j < DIM; j += 128) xs[j] = g_xn[row*DIM + j];
  for (int c = t; c < NCLS; c += 128) accs[c] = 0.f;
  __syncthreads();

  if (w == 0){
    for (int it = 0; it < CSEL; it++){
      float bv = -INFINITY; int bp = 0;
      for (int j = lane; j < NCAND; j += 32){
        float c = cv[j];
        if (c > bv){ bv = c; bp = j; }
      }
      #pragma unroll
      for (int o = 16; o; o >>= 1){
        float ov = __shfl_xor_sync(0xffffffffu, bv, o);
        int   op = __shfl_xor_sync(0xffffffffu, bp, o);
        if (ov > bv || (ov == bv && op < bp)){ bv = ov; bp = op; }
      }
      if (lane == 0){ selIdx[it] = ci[bp]; cv[bp] = -INFINITY; }
      __syncwarp();
    }
  }
  __syncthreads();

  for (int rr = 0; rr < CSEL/4; rr++){
    int c = w + 4*rr;
    const float* fr = mf + (size_t)selIdx[c] * DIM;
    float s = 0.f;
    #pragma unroll
    for (int j = 0; j < 8; j++){ int k = lane + 32*j; s += fr[k] * xs[k]; }
    #pragma unroll
    for (int o = 16; o; o >>= 1) s += __shfl_down_sync(0xffffffffu, s, o);
    if (lane == 0) ex[c] = s;
  }
  __syncthreads();

  if (t == 0){
    unsigned um = 0;
    float sval[KSEL]; int sfeat[KSEL];
    for (int it = 0; it < KSEL; it++){
      float bv = -INFINITY; int bc = 0;
      for (int c = 0; c < CSEL; c++){
        if (!((um >> c) & 1u) && ex[c] > bv){ bv = ex[c]; bc = c; }
      }
      um |= 1u << bc;
      sval[it] = bv; sfeat[it] = selIdx[bc];
    }
    float m = sval[0], sum = 0.f;
    for (int i = 0; i < KSEL; i++){ float e = expf((sval[i]-m)/TAUF); wgt[i] = e; sum += e; }
    float inv = 1.f / sum;
    for (int i = 0; i < KSEL; i++){ wgt[i] *= inv; flab[i] = lab[sfeat[i]]; }
    for (int i = 0; i < KSEL; i++) accs[flab[i]] += wgt[i];
  }
  __syncthreads();
  for (int c = t; c < NCLS; c += 128) out[(size_t)row*NCLS + c] = accs[c] * LSCALE;
}

// ---------------- dummy (profiling alignment: gemm at launch position 3) ----------------
__global__ void dummy_kernel(){}

// ---------------- launch ----------------
extern "C" void kernel_launch(void* const* d_in, const int* in_sizes, int n_in,
                              void* d_out, int out_size){
  const float* x    = (const float*)d_in[0];
  const float* mean = (const float*)d_in[1];
  const float* stdv = (const float*)d_in[2];
  const float* mf   = (const float*)d_in[3];
  const int*   lab  = (const int*)d_in[4];
  float* out = (float*)d_out;

  cudaFuncSetAttribute(gemm_topk_kernel, cudaFuncAttributeMaxDynamicSharedMemorySize, SM_TOTAL);

  setup_kernel<<<NQ, DIM>>>(x, mean, stdv, mf);   // pos 0
  dummy_kernel<<<1, 32>>>();                      // pos 1
  dummy_kernel<<<1, 32>>>();                      // pos 2
  gemm_topk_kernel<<<dim3(NQ/BM, NSTRIPE), NT, SM_TOTAL>>>();  // pos 3
  merge_kernel<<<NQ, 128>>>(mf, lab, out);        // pos 4
}